// round 16
// baseline (speedup 1.0000x reference)
#include <cuda_runtime.h>
#include <math.h>

// Biquad lowpass (fs=44100, fc=10000, Q=0.707).
// R16: warp-coalesced OUTS=4 + hybrid recursion math.
// R15's L1 was pinned at 78.5% by sector amplification: OUTS=8 puts lanes
// 32B apart, so every LDG.128/STG.128 half-fills 32 sectors (2x waste).
// Here each thread makes 4 consecutive outputs -> 16B lane stride, fully
// coalesced loads/stores (4 LDG.128 + 1 STG.128 per thread, all contiguous
// warp-wide). Math: y0,y1 seeded by 12-tap truncated FIR (trunc err ~3.8e-5,
// pole mag 0.4203), y2,y3 exact biquad recursion; immediate coefficients.

#define K_TAPS 12
#define OUTS   4
#define WIN    (K_TAPS + OUTS)  // 16 floats = 4 float4
#define T_LEN  160000

// Normalized biquad coefficients (validated R11/R15: rel_err 1.9e-5).
#define B0d 0.2513643704
#define B1d 0.5027287408
#define B2d 0.2513643704
#define A1d (-0.1712307400)
#define A2d 0.1766882000

// Truncated impulse response h[0..11], folded at compile time.
#define H0d (B0d)
#define H1d (B1d - A1d * H0d)
#define H2d (B2d - A1d * H1d - A2d * H0d)
#define H3d (-A1d * H2d - A2d * H1d)
#define H4d (-A1d * H3d - A2d * H2d)
#define H5d (-A1d * H4d - A2d * H3d)
#define H6d (-A1d * H5d - A2d * H4d)
#define H7d (-A1d * H6d - A2d * H5d)
#define H8d (-A1d * H7d - A2d * H6d)
#define H9d (-A1d * H8d - A2d * H7d)
#define H10d (-A1d * H9d - A2d * H8d)
#define H11d (-A1d * H10d - A2d * H9d)

__global__ __launch_bounds__(256) void lowpass_fir_kernel(
    const float* __restrict__ clip,
    float* __restrict__ out)
{
    const int t = (blockIdx.x * blockDim.x + threadIdx.x) * OUTS;
    if (t >= T_LEN) return;

    const size_t row = (size_t)blockIdx.y * T_LEN;
    const float* __restrict__ x = clip + row;

    float w[WIN];   // w[i] = x[t - 12 + i], i = 0..15

    if (t >= K_TAPS) {
        // Fast path: in-bounds, 16B-aligned (t mult of 4 -> t-12 mult of 4).
        // Warp-wide: lane stride 16B -> fully coalesced LDG.128 x4.
        const float4* __restrict__ p4 = reinterpret_cast<const float4*>(x + t - K_TAPS);
        #pragma unroll
        for (int i = 0; i < WIN / 4; i++) {
            float4 v = p4[i];
            w[4 * i + 0] = v.x;
            w[4 * i + 1] = v.y;
            w[4 * i + 2] = v.z;
            w[4 * i + 3] = v.w;
        }
    } else {
        // Left edge (t = 0, 4, 8 in the first block): zero-pad x[t'] for t' < 0.
        #pragma unroll
        for (int i = 0; i < WIN; i++) {
            int idx = t - K_TAPS + i;
            w[i] = (idx >= 0) ? x[idx] : 0.0f;
        }
    }

    // ---- FIR seeds (K=12), immediate coefficients ----
    // y0 = sum_k h[k] * w[12-k],  y1 = sum_k h[k] * w[13-k]
    float y0 = (float)H0d * w[12];
    float y1 = (float)H0d * w[13];
    y0 = fmaf((float)H1d,  w[11], y0);  y1 = fmaf((float)H1d,  w[12], y1);
    y0 = fmaf((float)H2d,  w[10], y0);  y1 = fmaf((float)H2d,  w[11], y1);
    y0 = fmaf((float)H3d,  w[9],  y0);  y1 = fmaf((float)H3d,  w[10], y1);
    y0 = fmaf((float)H4d,  w[8],  y0);  y1 = fmaf((float)H4d,  w[9],  y1);
    y0 = fmaf((float)H5d,  w[7],  y0);  y1 = fmaf((float)H5d,  w[8],  y1);
    y0 = fmaf((float)H6d,  w[6],  y0);  y1 = fmaf((float)H6d,  w[7],  y1);
    y0 = fmaf((float)H7d,  w[5],  y0);  y1 = fmaf((float)H7d,  w[6],  y1);
    y0 = fmaf((float)H8d,  w[4],  y0);  y1 = fmaf((float)H8d,  w[5],  y1);
    y0 = fmaf((float)H9d,  w[3],  y0);  y1 = fmaf((float)H9d,  w[4],  y1);
    y0 = fmaf((float)H10d, w[2],  y0);  y1 = fmaf((float)H10d, w[3],  y1);
    y0 = fmaf((float)H11d, w[1],  y0);  y1 = fmaf((float)H11d, w[2],  y1);

    // ---- Exact biquad recursion for y2, y3 ----
    float f2 = (float)B0d * w[14];
    f2 = fmaf((float)B1d, w[13], f2);
    f2 = fmaf((float)B2d, w[12], f2);
    f2 = fmaf(-(float)A1d, y1, f2);
    const float y2 = fmaf(-(float)A2d, y0, f2);

    float f3 = (float)B0d * w[15];
    f3 = fmaf((float)B1d, w[14], f3);
    f3 = fmaf((float)B2d, w[13], f3);
    f3 = fmaf(-(float)A1d, y2, f3);
    const float y3 = fmaf(-(float)A2d, y1, f3);

    float4 r;
    r.x = y0; r.y = y1; r.z = y2; r.w = y3;
    // Coalesced warp-wide STG.128 (lane stride 16B).
    *reinterpret_cast<float4*>(out + row + t) = r;
}

extern "C" void kernel_launch(void* const* d_in, const int* in_sizes, int n_in,
                              void* d_out, int out_size)
{
    const float* clip = (const float*)d_in[0];
    float* out = (float*)d_out;

    const int total = in_sizes[0];
    const int batch = total / T_LEN;   // 128

    const int threads = 256;
    const int outs_per_block = threads * OUTS;                          // 1024
    const int blocks_x = (T_LEN + outs_per_block - 1) / outs_per_block; // 157
    dim3 grid(blocks_x, batch);

    lowpass_fir_kernel<<<grid, threads>>>(clip, out);
}

// round 17
// speedup vs baseline: 1.0576x; 1.0576x over previous
#include <cuda_runtime.h>
#include <math.h>

// Biquad lowpass (fs=44100, fc=10000, Q=0.707).
// R17 = R15 (best bench 29.15us: 8 outputs/thread, 20-float register window,
// 5x LDG.128, hybrid FIR-seed + exact IIR recursion, immediate coefficients)
// + streaming cache hints: __ldcs input loads (stream-once, evict-first) and
// __stcs output stores. Bench is pinned at the sustained mixed-r/w HBM floor
// (164MB / ~5.6TB/s ~ 29us); evict-first on both streams maximizes L2 space
// available for write coalescing at that floor.

#define K_TAPS 12
#define OUTS   8
#define WIN    (K_TAPS + OUTS)  // 20 floats = 5 float4
#define T_LEN  160000

// Normalized biquad coefficients (validated R11/R15: rel_err 1.9e-5).
#define B0d 0.2513643704
#define B1d 0.5027287408
#define B2d 0.2513643704
#define A1d (-0.1712307400)
#define A2d 0.1766882000

// Truncated impulse response h[0..11], folded at compile time.
#define H0d (B0d)
#define H1d (B1d - A1d * H0d)
#define H2d (B2d - A1d * H1d - A2d * H0d)
#define H3d (-A1d * H2d - A2d * H1d)
#define H4d (-A1d * H3d - A2d * H2d)
#define H5d (-A1d * H4d - A2d * H3d)
#define H6d (-A1d * H5d - A2d * H4d)
#define H7d (-A1d * H6d - A2d * H5d)
#define H8d (-A1d * H7d - A2d * H6d)
#define H9d (-A1d * H8d - A2d * H7d)
#define H10d (-A1d * H9d - A2d * H8d)
#define H11d (-A1d * H10d - A2d * H9d)

__global__ __launch_bounds__(256) void lowpass_fir_kernel(
    const float* __restrict__ clip,
    float* __restrict__ out)
{
    const int t = (blockIdx.x * blockDim.x + threadIdx.x) * OUTS;
    if (t >= T_LEN) return;

    const size_t row = (size_t)blockIdx.y * T_LEN;
    const float* __restrict__ x = clip + row;

    float w[WIN];   // w[i] = x[t - 12 + i], i = 0..19

    if (t >= K_TAPS) {
        // Fast path: in-bounds, 16B-aligned (t mult of 8 -> t-12 mult of 4).
        const float4* __restrict__ p4 = reinterpret_cast<const float4*>(x + t - K_TAPS);
        #pragma unroll
        for (int i = 0; i < WIN / 4; i++) {
            float4 v = __ldcs(p4 + i);   // streaming: evict-first in L2
            w[4 * i + 0] = v.x;
            w[4 * i + 1] = v.y;
            w[4 * i + 2] = v.z;
            w[4 * i + 3] = v.w;
        }
    } else {
        // Left edge (t = 0 or 8): zero-pad x[t'] for t' < 0.
        #pragma unroll
        for (int i = 0; i < WIN; i++) {
            int idx = t - K_TAPS + i;
            w[i] = (idx >= 0) ? x[idx] : 0.0f;
        }
    }

    // ---- FIR seeds (K=12), immediate coefficients ----
    // y0 = sum_k h[k] * w[12-k],  y1 = sum_k h[k] * w[13-k]
    float y0 = (float)H0d * w[12];
    float y1 = (float)H0d * w[13];
    y0 = fmaf((float)H1d,  w[11], y0);  y1 = fmaf((float)H1d,  w[12], y1);
    y0 = fmaf((float)H2d,  w[10], y0);  y1 = fmaf((float)H2d,  w[11], y1);
    y0 = fmaf((float)H3d,  w[9],  y0);  y1 = fmaf((float)H3d,  w[10], y1);
    y0 = fmaf((float)H4d,  w[8],  y0);  y1 = fmaf((float)H4d,  w[9],  y1);
    y0 = fmaf((float)H5d,  w[7],  y0);  y1 = fmaf((float)H5d,  w[8],  y1);
    y0 = fmaf((float)H6d,  w[6],  y0);  y1 = fmaf((float)H6d,  w[7],  y1);
    y0 = fmaf((float)H7d,  w[5],  y0);  y1 = fmaf((float)H7d,  w[6],  y1);
    y0 = fmaf((float)H8d,  w[4],  y0);  y1 = fmaf((float)H8d,  w[5],  y1);
    y0 = fmaf((float)H9d,  w[3],  y0);  y1 = fmaf((float)H9d,  w[4],  y1);
    y0 = fmaf((float)H10d, w[2],  y0);  y1 = fmaf((float)H10d, w[3],  y1);
    y0 = fmaf((float)H11d, w[1],  y0);  y1 = fmaf((float)H11d, w[2],  y1);

    // ---- Exact biquad recursion for y2..y7 ----
    float y[OUTS];
    y[0] = y0; y[1] = y1;
    #pragma unroll
    for (int n = 2; n < OUTS; n++) {
        float f = (float)B0d * w[12 + n];
        f = fmaf((float)B1d, w[11 + n], f);
        f = fmaf((float)B2d, w[10 + n], f);
        f = fmaf(-(float)A1d, y[n - 1], f);
        y[n] = fmaf(-(float)A2d, y[n - 2], f);
    }

    float4 r0, r1;
    r0.x = y[0]; r0.y = y[1]; r0.z = y[2]; r0.w = y[3];
    r1.x = y[4]; r1.y = y[5]; r1.z = y[6]; r1.w = y[7];
    float4* __restrict__ o4 = reinterpret_cast<float4*>(out + row + t);
    __stcs(o4 + 0, r0);   // streaming store: evict-first
    __stcs(o4 + 1, r1);
}

extern "C" void kernel_launch(void* const* d_in, const int* in_sizes, int n_in,
                              void* d_out, int out_size)
{
    const float* clip = (const float*)d_in[0];
    float* out = (float*)d_out;

    const int total = in_sizes[0];
    const int batch = total / T_LEN;   // 128

    const int threads = 256;
    const int outs_per_block = threads * OUTS;                          // 2048
    const int blocks_x = (T_LEN + outs_per_block - 1) / outs_per_block; // 79
    dim3 grid(blocks_x, batch);

    lowpass_fir_kernel<<<grid, threads>>>(clip, out);
}